// round 11
// baseline (speedup 1.0000x reference)
#include <cuda_runtime.h>
#include <cuda_bf16.h>
#include <cuda_fp16.h>
#include <math.h>
#include <stdint.h>

#define NN 10000
#define EE 160000
#define HH 4
#define MPAD 10112   // 79 * 128
#define EXPCAP 256

// ---------------- static scratch ----------------
__device__ float g_C [NN * 1408];              // [N, NCATP] (res|el|er; feat cols unused)
__device__ __half g_F16[NN * 1024];            // [N, 4*D] fp16 feat gather table
__device__ __nv_bfloat16 g_A2[MPAD * 384];     // [M, 384] = [hi | hi | lo]
__device__ __nv_bfloat16 g_B2[384 * 3712];     // 4 layers of [384][NCATP_l]
__device__ float g_hA  [NN * 128];
__device__ float g_hB  [NN * 128];
__device__ float g_eedge[EE * HH];
__device__ int   g_off [NN + 1];
__device__ int   g_cur [NN];
__device__ int   g_csrc[EE];
__device__ int   g_ceid[EE];
__device__ float g_wev [64 * HH];

__device__ __forceinline__ uint32_t smem_u32(const void* p) {
    return (uint32_t)__cvta_generic_to_shared(p);
}
__device__ __forceinline__ void cpa16(uint32_t s, const void* g) {
    asm volatile("cp.async.cg.shared.global [%0], [%1], 16;" :: "r"(s), "l"(g));
}
__device__ __forceinline__ void bf16split(float v, __nv_bfloat16& hi, __nv_bfloat16& lo) {
    hi = __float2bfloat16(v);
    lo = __float2bfloat16(v - __bfloat162float(hi));
}

// ---------------- mega-prep (unchanged) ----------------
__global__ void prep_kernel(
    const float* __restrict__ x0,
    const float* W0, const float* W1, const float* W2, const float* W3,
    const float* r0, const float* r1, const float* r2, const float* r3,
    const float* al0, const float* al1, const float* al2, const float* al3,
    const float* ar0, const float* ar1, const float* ar2, const float* ar3,
    const float* We, const float* ae) {
    const float* W[4]  = {W0, W1, W2, W3};
    const float* rs[4] = {r0, r1, r2, r3};
    const float* al[4] = {al0, al1, al2, al3};
    const float* ar[4] = {ar0, ar1, ar2, ar3};
    const int Dl[4]    = {128, 128, 128, 256};
    const int NC[4]    = {768, 768, 768, 1408};
    const int B2OFF[4] = {0, 294912, 589824, 884736};

    int blk = blockIdx.x, tid = threadIdx.x;

    if (blk < 5000) {
        int i = blk * 256 + tid;
        int row = i >> 7, col = i & 127;
        __nv_bfloat16 hi, lo;
        bf16split(x0[i], hi, lo);
        size_t base = (size_t)row * 384 + col;
        g_A2[base]       = hi;
        g_A2[base + 128] = hi;
        g_A2[base + 256] = lo;
    } else if (blk < 6856) {
        int l, base;
        if (blk < 5384)      { l = 0; base = blk - 5000; }
        else if (blk < 5768) { l = 1; base = blk - 5384; }
        else if (blk < 6152) { l = 2; base = blk - 5768; }
        else                 { l = 3; base = blk - 6152; }
        int NCATP = NC[l], D = Dl[l];
        int t = base * 256 + tid;
        int i = t / NCATP, c = t - i * NCATP;
        if (c >= 5 * D && c < 5 * D + 8) return;
        float v = 0.f;
        if (c < 4 * D)      v = W[l][(size_t)i * 4 * D + c];
        else if (c < 5 * D) v = rs[l][(size_t)i * D + (c - 4 * D)];
        __nv_bfloat16 hi, lo;
        bf16split(v, hi, lo);
        size_t o = B2OFF[l];
        g_B2[o + (size_t)i * NCATP + c]         = hi;
        g_B2[o + (size_t)(i + 128) * NCATP + c] = lo;
        g_B2[o + (size_t)(i + 256) * NCATP + c] = hi;
    } else if (blk < 6864) {
        int lid = blk - 6856;
        int l = lid >> 1;
        int t = (lid & 1) * 256 + tid;
        int NCATP = NC[l], D = Dl[l];
        int i = t >> 2, h = t & 3;
        const float* wr = W[l] + (size_t)(i * HH + h) * D;
        const float* vl = al[l] + h * D;
        const float* vr = ar[l] + h * D;
        float sl = 0.f, sr = 0.f;
        for (int d = 0; d < D; d++) {
            float w = wr[d];
            sl = fmaf(w, vl[d], sl);
            sr = fmaf(w, vr[d], sr);
        }
        size_t o = B2OFF[l];
        int cL = 5 * D + h, cR = 5 * D + 4 + h;
        __nv_bfloat16 hi, lo;
        bf16split(sl, hi, lo);
        g_B2[o + (size_t)i * NCATP + cL] = hi;
        g_B2[o + (size_t)(i + 128) * NCATP + cL] = lo;
        g_B2[o + (size_t)(i + 256) * NCATP + cL] = hi;
        bf16split(sr, hi, lo);
        g_B2[o + (size_t)i * NCATP + cR] = hi;
        g_B2[o + (size_t)(i + 128) * NCATP + cR] = lo;
        g_B2[o + (size_t)(i + 256) * NCATP + cR] = hi;
    } else if (blk == 6864) {
        int t = tid;
        int i = t >> 2, h = t & 3;
        const float* wr = We + (size_t)(i * HH + h) * 128;
        const float* a  = ae + h * 128;
        float s = 0.f;
        for (int d = 0; d < 128; d++) s = fmaf(wr[d], a[d], s);
        g_wev[t] = s;
    } else {
        int i = (blk - 6865) * 256 + tid;
        if (i < NN) g_cur[i] = 0;
    }
}

// ---------------- bf16 HMMA GEMM (unchanged from R10) ----------------
__global__ void __launch_bounds__(256) mma_gemm(
        const __nv_bfloat16* __restrict__ A2, const __nv_bfloat16* __restrict__ B2,
        float* __restrict__ C, __half* __restrict__ F,
        int Nc, int nFeat) {
    __shared__ __nv_bfloat16 As[2][128][40];
    __shared__ __nv_bfloat16 Bs[2][32][136];
    int tid = threadIdx.x, wid = tid >> 5, lane = tid & 31;
    int wm = (wid & 1) * 64;
    int wn = (wid >> 1) * 32;
    int rowBase = blockIdx.x * 128;
    int colBase = blockIdx.y * 128;

    float c[4][4][4];
#pragma unroll
    for (int i = 0; i < 4; i++)
#pragma unroll
        for (int j = 0; j < 4; j++)
#pragma unroll
            for (int r = 0; r < 4; r++) c[i][j][r] = 0.f;

    int ra0 = tid >> 2,          ca0 = (tid & 3) * 8;
    int ra1 = (tid + 256) >> 2,  ca1 = ((tid + 256) & 3) * 8;
    int rb0 = tid >> 4,          cb0 = (tid & 15) * 8;
    int rb1 = (tid + 256) >> 4,  cb1 = ((tid + 256) & 15) * 8;

#define LOAD_STAGE(kb, st) do { \
        int k0 = (kb) * 32; \
        cpa16(smem_u32(&As[st][ra0][ca0]), A2 + (size_t)(rowBase + ra0) * 384 + k0 + ca0); \
        cpa16(smem_u32(&As[st][ra1][ca1]), A2 + (size_t)(rowBase + ra1) * 384 + k0 + ca1); \
        cpa16(smem_u32(&Bs[st][rb0][cb0]), B2 + (size_t)(k0 + rb0) * Nc + colBase + cb0); \
        cpa16(smem_u32(&Bs[st][rb1][cb1]), B2 + (size_t)(k0 + rb1) * Nc + colBase + cb1); \
        asm volatile("cp.async.commit_group;" ::: "memory"); \
    } while (0)

    LOAD_STAGE(0, 0);

    for (int kb = 0; kb < 12; kb++) {
        int cur = kb & 1;
        asm volatile("cp.async.wait_group 0;" ::: "memory");
        __syncthreads();
        if (kb < 11) LOAD_STAGE(kb + 1, cur ^ 1);

        uint32_t a[2][4][4], b[2][4][2];
#pragma unroll
        for (int kh = 0; kh < 2; kh++) {
            int kk = kh * 16;
#pragma unroll
            for (int i = 0; i < 4; i++) {
                uint32_t ad = smem_u32(&As[cur][wm + i * 16 + (lane & 15)][kk + (lane >> 4) * 8]);
                asm volatile("ldmatrix.sync.aligned.m8n8.x4.shared.b16 {%0,%1,%2,%3}, [%4];"
                    : "=r"(a[kh][i][0]), "=r"(a[kh][i][1]), "=r"(a[kh][i][2]), "=r"(a[kh][i][3]) : "r"(ad));
            }
#pragma unroll
            for (int j2 = 0; j2 < 2; j2++) {
                uint32_t bd = smem_u32(&Bs[cur][kk + (lane & 15)][wn + j2 * 16 + (lane >> 4) * 8]);
                asm volatile("ldmatrix.sync.aligned.m8n8.x4.trans.shared.b16 {%0,%1,%2,%3}, [%4];"
                    : "=r"(b[kh][j2 * 2][0]), "=r"(b[kh][j2 * 2][1]),
                      "=r"(b[kh][j2 * 2 + 1][0]), "=r"(b[kh][j2 * 2 + 1][1]) : "r"(bd));
            }
        }
#pragma unroll
        for (int kh = 0; kh < 2; kh++)
#pragma unroll
            for (int i = 0; i < 4; i++)
#pragma unroll
                for (int j = 0; j < 4; j++)
                    asm volatile("mma.sync.aligned.m16n8k16.row.col.f32.bf16.bf16.f32 "
                        "{%0,%1,%2,%3}, {%4,%5,%6,%7}, {%8,%9}, {%0,%1,%2,%3};"
                        : "+f"(c[i][j][0]), "+f"(c[i][j][1]), "+f"(c[i][j][2]), "+f"(c[i][j][3])
                        : "r"(a[kh][i][0]), "r"(a[kh][i][1]), "r"(a[kh][i][2]), "r"(a[kh][i][3]),
                          "r"(b[kh][j][0]), "r"(b[kh][j][1]));
    }
#undef LOAD_STAGE

    if (colBase < nFeat) {
#pragma unroll
        for (int i = 0; i < 4; i++) {
            int row = rowBase + wm + i * 16 + (lane >> 2);
#pragma unroll
            for (int j = 0; j < 4; j++) {
                int col = colBase + wn + j * 8 + (lane & 3) * 2;
                if (row < NN)
                    *(__half2*)(F + (size_t)row * nFeat + col) = __floats2half2_rn(c[i][j][0], c[i][j][1]);
                if (row + 8 < NN)
                    *(__half2*)(F + (size_t)(row + 8) * nFeat + col) = __floats2half2_rn(c[i][j][2], c[i][j][3]);
            }
        }
    } else {
#pragma unroll
        for (int i = 0; i < 4; i++) {
            int row = rowBase + wm + i * 16 + (lane >> 2);
#pragma unroll
            for (int j = 0; j < 4; j++) {
                int col = colBase + wn + j * 8 + (lane & 3) * 2;
                if (row < NN)
                    *(float2*)(C + (size_t)row * Nc + col) = make_float2(c[i][j][0], c[i][j][1]);
                if (row + 8 < NN)
                    *(float2*)(C + (size_t)(row + 8) * Nc + col) = make_float2(c[i][j][2], c[i][j][3]);
            }
        }
    }
}

// ---------------- merged scatter + eedge ----------------
__global__ void __launch_bounds__(256) post_kernel(
        const int* __restrict__ src, const int* __restrict__ dst,
        const float* __restrict__ ef) {
    int blk = blockIdx.x, tid = threadIdx.x;
    if (blk < EE / 64) {
        __shared__ float sf[64][68];
        __shared__ float sw[64 * HH];
        int e0 = blk * 64;
        sw[tid] = g_wev[tid];
#pragma unroll
        for (int j = 0; j < 4; j++) {
            int idx = tid + j * 256;
            int e = idx >> 4, q = idx & 15;
            float4 v = *(const float4*)(ef + (size_t)(e0 + e) * 64 + q * 4);
            *(float4*)&sf[e][q * 4] = v;
        }
        __syncthreads();
        int e = tid >> 2, h = tid & 3;
        float acc = 0.f;
#pragma unroll
        for (int d = 0; d < 64; d++)
            acc = fmaf(sf[e][d], sw[d * 4 + h], acc);
        g_eedge[(size_t)(e0 + e) * 4 + h] = acc;
    } else {
        int e = (blk - EE / 64) * 256 + tid;
        if (e < EE) {
            int p = atomicAdd(&g_cur[dst[e]], 1);
            g_csrc[p] = src[e];
            g_ceid[p] = e;
        }
    }
}

// ---------------- CSR count + scan ----------------
__global__ void count_kernel(const int* __restrict__ dst) {
    int e = blockIdx.x * blockDim.x + threadIdx.x;
    if (e < EE) atomicAdd(&g_cur[dst[e]], 1);
}
__global__ void scan_kernel() {
    __shared__ int sh[1024];
    int t = threadIdx.x;
    int vals[10];
    int base = t * 10;
    int s = 0;
#pragma unroll
    for (int j = 0; j < 10; j++) {
        int idx = base + j;
        int v = (idx < NN) ? g_cur[idx] : 0;
        vals[j] = s;
        s += v;
    }
    sh[t] = s;
    __syncthreads();
    for (int off = 1; off < 1024; off <<= 1) {
        int v = (t >= off) ? sh[t - off] : 0;
        __syncthreads();
        sh[t] += v;
        __syncthreads();
    }
    int excl = (t > 0) ? sh[t - 1] : 0;
#pragma unroll
    for (int j = 0; j < 10; j++) {
        int idx = base + j;
        if (idx < NN) {
            int o = excl + vals[j];
            g_off[idx] = o;
            g_cur[idx] = o;
        }
    }
    if (t == 1023) g_off[NN] = sh[1023];
}

// ---------------- FUSED softmax + aggregation ---------------------------------
// Phase 1: ALL threads compute exp-partials (thread's h = tid&3, stash in smem).
// Phase 2: gather loop reads alpha from smem (fallback: recompute).
template <int D, int WRITE_BF16>
__global__ void agg_fused(const float* __restrict__ C, const __half* __restrict__ F,
                          float* __restrict__ out, int NCATP, int use_edge) {
    constexpr int DG = D / 4;
    constexpr int T = D;          // block threads
    constexpr int FW = 4 * D;
    __shared__ float s_exp[EXPCAP][4];
    __shared__ float s_part[T];
    __shared__ float s_inv[4];
    __shared__ float4 s_red[T];

    int n = blockIdx.x;
    int tid = threadIdx.x;
    int b = g_off[n], e = g_off[n + 1];
    int deg = e - b;
    int colE = 5 * D;

    // ---- phase 1: parallel single-pass softmax sums ----
    {
        int h1 = tid & 3;
        float ern = C[(size_t)n * NCATP + colE + 4 + h1];
        float psum = 0.f;
        int deg4 = deg * 4;
        for (int t = tid; t < deg4; t += T) {
            int q = t >> 2;
            int p = b + q;
            float ee = C[(size_t)g_csrc[p] * NCATP + colE + h1] + ern;
            if (use_edge) ee += g_eedge[(size_t)g_ceid[p] * 4 + h1];
            ee = ee > 0.f ? ee : 0.2f * ee;
            float ex = __expf(ee);
            if (q < EXPCAP) s_exp[q][h1] = ex;
            psum += ex;
        }
        s_part[tid] = psum;
    }
    __syncthreads();
    if (tid < 4) {
        float s = 0.f;
        for (int j = tid; j < T; j += 4) s += s_part[j];
        s_inv[tid] = 1.f / (s + 1e-9f);
    }
    __syncthreads();

    // ---- phase 2: gather (2x unrolled) ----
    int h = tid / DG;
    int dg = tid % DG;
    float ern2 = C[(size_t)n * NCATP + colE + 4 + h];
    float4 acc = make_float4(0.f, 0.f, 0.f, 0.f);
    const __half* fbase = F + h * D + dg * 4;

#define GET_ALPHA(q, pp, dst_a) do { \
        if ((q) < EXPCAP) dst_a = s_exp[q][h]; \
        else { \
            float ee = C[(size_t)g_csrc[pp] * NCATP + colE + h] + ern2; \
            if (use_edge) ee += g_eedge[(size_t)g_ceid[pp] * 4 + h]; \
            ee = ee > 0.f ? ee : 0.2f * ee; \
            dst_a = __expf(ee); \
        } \
    } while (0)

    int q = 0;
    for (; q + 2 <= deg; q += 2) {
        int p0 = b + q, p1 = b + q + 1;
        int s0 = g_csrc[p0], s1 = g_csrc[p1];
        float a0, a1;
        GET_ALPHA(q, p0, a0);
        GET_ALPHA(q + 1, p1, a1);
        uint2 r0 = *(const uint2*)(fbase + (size_t)s0 * FW);
        uint2 r1 = *(const uint2*)(fbase + (size_t)s1 * FW);
        float2 f00 = __half22float2(*reinterpret_cast<__half2*>(&r0.x));
        float2 f01 = __half22float2(*reinterpret_cast<__half2*>(&r0.y));
        float2 f10 = __half22float2(*reinterpret_cast<__half2*>(&r1.x));
        float2 f11 = __half22float2(*reinterpret_cast<__half2*>(&r1.y));
        acc.x = fmaf(a0, f00.x, acc.x);
        acc.y = fmaf(a0, f00.y, acc.y);
        acc.z = fmaf(a0, f01.x, acc.z);
        acc.w = fmaf(a0, f01.y, acc.w);
        acc.x = fmaf(a1, f10.x, acc.x);
        acc.y = fmaf(a1, f10.y, acc.y);
        acc.z = fmaf(a1, f11.x, acc.z);
        acc.w = fmaf(a1, f11.y, acc.w);
    }
    if (q < deg) {
        int p0 = b + q;
        int s0 = g_csrc[p0];
        float a0;
        GET_ALPHA(q, p0, a0);
        uint2 r0 = *(const uint2*)(fbase + (size_t)s0 * FW);
        float2 f00 = __half22float2(*reinterpret_cast<__half2*>(&r0.x));
        float2 f01 = __half22float2(*reinterpret_cast<__half2*>(&r0.y));
        acc.x = fmaf(a0, f00.x, acc.x);
        acc.y = fmaf(a0, f00.y, acc.y);
        acc.z = fmaf(a0, f01.x, acc.z);
        acc.w = fmaf(a0, f01.y, acc.w);
    }
#undef GET_ALPHA

    float sc = s_inv[h] * 0.25f;
    acc.x *= sc; acc.y *= sc; acc.z *= sc; acc.w *= sc;

    s_red[tid] = acc;
    __syncthreads();
    if (tid < DG) {
        float4 q0 = s_red[tid], q1 = s_red[DG + tid], q2 = s_red[2 * DG + tid], q3 = s_red[3 * DG + tid];
        float4 rr = *(const float4*)(C + (size_t)n * NCATP + 4 * D + tid * 4);
        float4 o;
        o.x = fmaxf(q0.x + q1.x + q2.x + q3.x + rr.x, 0.f);
        o.y = fmaxf(q0.y + q1.y + q2.y + q3.y + rr.y, 0.f);
        o.z = fmaxf(q0.z + q1.z + q2.z + q3.z + rr.z, 0.f);
        o.w = fmaxf(q0.w + q1.w + q2.w + q3.w + rr.w, 0.f);
        *(float4*)(out + (size_t)n * D + tid * 4) = o;
        if (WRITE_BF16) {
            size_t base = (size_t)n * 384 + tid * 4;
            float vv[4] = {o.x, o.y, o.z, o.w};
#pragma unroll
            for (int j = 0; j < 4; j++) {
                __nv_bfloat16 hi, lo;
                bf16split(vv[j], hi, lo);
                g_A2[base + j]       = hi;
                g_A2[base + 128 + j] = hi;
                g_A2[base + 256 + j] = lo;
            }
        }
    }
}

// ---------------- host orchestration ----------------
extern "C" void kernel_launch(void* const* d_in, const int* in_sizes, int n_in,
                              void* d_out, int out_size) {
    const float* x0  = (const float*)d_in[0];
    const float* ef  = (const float*)d_in[1];
    const int*   src = (const int*)d_in[2];
    const int*   dst = (const int*)d_in[3];

    float *p_C, *p_hA, *p_hB;
    __half* p_F;
    __nv_bfloat16 *p_A2, *p_B2;
    cudaGetSymbolAddress((void**)&p_C,  g_C);
    cudaGetSymbolAddress((void**)&p_F,  g_F16);
    cudaGetSymbolAddress((void**)&p_hA, g_hA);
    cudaGetSymbolAddress((void**)&p_hB, g_hB);
    cudaGetSymbolAddress((void**)&p_A2, g_A2);
    cudaGetSymbolAddress((void**)&p_B2, g_B2);

    float* houts[4]  = {p_hA, p_hB, p_hA, (float*)d_out};
    int Dl[4]        = {128, 128, 128, 256};
    int NCATP_[4]    = {768, 768, 768, 1408};
    size_t B2OFF[4]  = {0, 294912, 589824, 884736};

    prep_kernel<<<6905, 256>>>(x0,
        (const float*)d_in[4],  (const float*)d_in[10], (const float*)d_in[14], (const float*)d_in[18],
        (const float*)d_in[9],  (const float*)d_in[13], (const float*)d_in[17], (const float*)d_in[21],
        (const float*)d_in[6],  (const float*)d_in[11], (const float*)d_in[15], (const float*)d_in[19],
        (const float*)d_in[7],  (const float*)d_in[12], (const float*)d_in[16], (const float*)d_in[20],
        (const float*)d_in[5],  (const float*)d_in[8]);
    count_kernel<<<(EE + 255) / 256, 256>>>(dst);
    scan_kernel<<<1, 1024>>>();
    {   // launch #4: L0 GEMM (profiled)
        dim3 gg(MPAD / 128, NCATP_[0] / 128);
        mma_gemm<<<gg, 256>>>(p_A2, p_B2 + B2OFF[0], p_C, p_F, NCATP_[0], 4 * Dl[0]);
    }
    post_kernel<<<EE / 64 + (EE + 255) / 256, 256>>>(src, dst, ef);
    agg_fused<128, 1><<<NN, 128>>>(p_C, p_F, houts[0], NCATP_[0], 1);

    for (int L = 1; L < 4; L++) {
        int D = Dl[L];
        int NCATP = NCATP_[L];
        dim3 gg(MPAD / 128, NCATP / 128);
        mma_gemm<<<gg, 256>>>(p_A2, p_B2 + B2OFF[L], p_C, p_F, NCATP, 4 * D);
        if (D == 128) {
            agg_fused<128, 1><<<NN, 128>>>(p_C, p_F, houts[L], NCATP, 0);
        } else {
            agg_fused<256, 0><<<NN, 256>>>(p_C, p_F, houts[L], NCATP, 0);
        }
    }
}

// round 12
// speedup vs baseline: 1.0930x; 1.0930x over previous
#include <cuda_runtime.h>
#include <cuda_fp16.h>
#include <math.h>
#include <stdint.h>

#define NN 10000
#define EE 160000
#define HH 4
#define MPAD 10112   // 79 * 128

// ---------------- static scratch ----------------
__device__ float g_C [NN * 1408];              // [N, NCATP] (res|el|er; feat cols unused)
__device__ __half g_F16[NN * 1024];            // [N, 4*D] fp16 feat gather table
__device__ __half g_A2[MPAD * 256];            // [M, 256] = [fp16 hi | fp16 lo]
__device__ __half g_B2[256 * 3712];            // 4 layers of [256][NCATP_l] (b duplicated)
__device__ float g_hA  [NN * 128];
__device__ float g_hB  [NN * 128];
__device__ float g_eedge[EE * HH];
__device__ float g_inv [NN * HH];
__device__ float g_alpha[EE * HH];
__device__ int   g_off [NN + 1];
__device__ int   g_cur [NN];
__device__ int   g_csrc[EE];
__device__ int   g_ceid[EE];
__device__ float g_wev [64 * HH];

__device__ __forceinline__ uint32_t smem_u32(const void* p) {
    return (uint32_t)__cvta_generic_to_shared(p);
}
__device__ __forceinline__ void cpa16(uint32_t s, const void* g) {
    asm volatile("cp.async.cg.shared.global [%0], [%1], 16;" :: "r"(s), "l"(g));
}
// fp16 2-term split: v = hi + lo to ~2^-22 relative
__device__ __forceinline__ void f16split(float v, __half& hi, __half& lo) {
    hi = __float2half(v);
    lo = __float2half(v - __half2float(hi));
}

// ---------------- mega-prep ----------------
__global__ void prep_kernel(
    const float* __restrict__ x0,
    const float* W0, const float* W1, const float* W2, const float* W3,
    const float* r0, const float* r1, const float* r2, const float* r3,
    const float* al0, const float* al1, const float* al2, const float* al3,
    const float* ar0, const float* ar1, const float* ar2, const float* ar3,
    const float* We, const float* ae) {
    const float* W[4]  = {W0, W1, W2, W3};
    const float* rs[4] = {r0, r1, r2, r3};
    const float* al[4] = {al0, al1, al2, al3};
    const float* ar[4] = {ar0, ar1, ar2, ar3};
    const int Dl[4]    = {128, 128, 128, 256};
    const int NC[4]    = {768, 768, 768, 1408};
    const int B2OFF[4] = {0, 196608, 393216, 589824};

    int blk = blockIdx.x, tid = threadIdx.x;

    if (blk < 5000) {                       // conv_x: x0 -> A2 fp16 [hi|lo]
        int i = blk * 256 + tid;
        int row = i >> 7, col = i & 127;
        __half hi, lo;
        f16split(x0[i], hi, lo);
        size_t base = (size_t)row * 256 + col;
        g_A2[base]       = hi;
        g_A2[base + 128] = lo;
    } else if (blk < 6856) {                // B2 builds (b duplicated in both K halves)
        int l, base;
        if (blk < 5384)      { l = 0; base = blk - 5000; }
        else if (blk < 5768) { l = 1; base = blk - 5384; }
        else if (blk < 6152) { l = 2; base = blk - 5768; }
        else                 { l = 3; base = blk - 6152; }
        int NCATP = NC[l], D = Dl[l];
        int t = base * 256 + tid;
        int i = t / NCATP, c = t - i * NCATP;
        if (c >= 5 * D && c < 5 * D + 8) return;
        float v = 0.f;
        if (c < 4 * D)      v = W[l][(size_t)i * 4 * D + c];
        else if (c < 5 * D) v = rs[l][(size_t)i * D + (c - 4 * D)];
        __half hv = __float2half(v);
        size_t o = B2OFF[l];
        g_B2[o + (size_t)i * NCATP + c]         = hv;
        g_B2[o + (size_t)(i + 128) * NCATP + c] = hv;
    } else if (blk < 6864) {                // contract: el/er columns
        int lid = blk - 6856;
        int l = lid >> 1;
        int t = (lid & 1) * 256 + tid;
        int NCATP = NC[l], D = Dl[l];
        int i = t >> 2, h = t & 3;
        const float* wr = W[l] + (size_t)(i * HH + h) * D;
        const float* vl = al[l] + h * D;
        const float* vr = ar[l] + h * D;
        float sl = 0.f, sr = 0.f;
        for (int d = 0; d < D; d++) {
            float w = wr[d];
            sl = fmaf(w, vl[d], sl);
            sr = fmaf(w, vr[d], sr);
        }
        size_t o = B2OFF[l];
        int cL = 5 * D + h, cR = 5 * D + 4 + h;
        __half hl16 = __float2half(sl), hr16 = __float2half(sr);
        g_B2[o + (size_t)i * NCATP + cL]         = hl16;
        g_B2[o + (size_t)(i + 128) * NCATP + cL] = hl16;
        g_B2[o + (size_t)i * NCATP + cR]         = hr16;
        g_B2[o + (size_t)(i + 128) * NCATP + cR] = hr16;
    } else if (blk == 6864) {               // wev = We . ae
        int t = tid;
        int i = t >> 2, h = t & 3;
        const float* wr = We + (size_t)(i * HH + h) * 128;
        const float* a  = ae + h * 128;
        float s = 0.f;
        for (int d = 0; d < 128; d++) s = fmaf(wr[d], a[d], s);
        g_wev[t] = s;
    } else {                                // zero_cur
        int i = (blk - 6865) * 256 + tid;
        if (i < NN) g_cur[i] = 0;
    }
}

// ---------------- fp16 HMMA GEMM: C[M,Nc] = A2[M,256] @ B2[256,Nc] ----------
__global__ void __launch_bounds__(256) mma_gemm(
        const __half* __restrict__ A2, const __half* __restrict__ B2,
        float* __restrict__ C, __half* __restrict__ F,
        int Nc, int nFeat) {
    __shared__ __half As[2][128][40];
    __shared__ __half Bs[2][32][136];
    int tid = threadIdx.x, wid = tid >> 5, lane = tid & 31;
    int wm = (wid & 1) * 64;
    int wn = (wid >> 1) * 32;
    int rowBase = blockIdx.x * 128;
    int colBase = blockIdx.y * 128;

    float c[4][4][4];
#pragma unroll
    for (int i = 0; i < 4; i++)
#pragma unroll
        for (int j = 0; j < 4; j++)
#pragma unroll
            for (int r = 0; r < 4; r++) c[i][j][r] = 0.f;

    int ra0 = tid >> 2,          ca0 = (tid & 3) * 8;
    int ra1 = (tid + 256) >> 2,  ca1 = ((tid + 256) & 3) * 8;
    int rb0 = tid >> 4,          cb0 = (tid & 15) * 8;
    int rb1 = (tid + 256) >> 4,  cb1 = ((tid + 256) & 15) * 8;

#define LOAD_STAGE(kb, st) do { \
        int k0 = (kb) * 32; \
        cpa16(smem_u32(&As[st][ra0][ca0]), A2 + (size_t)(rowBase + ra0) * 256 + k0 + ca0); \
        cpa16(smem_u32(&As[st][ra1][ca1]), A2 + (size_t)(rowBase + ra1) * 256 + k0 + ca1); \
        cpa16(smem_u32(&Bs[st][rb0][cb0]), B2 + (size_t)(k0 + rb0) * Nc + colBase + cb0); \
        cpa16(smem_u32(&Bs[st][rb1][cb1]), B2 + (size_t)(k0 + rb1) * Nc + colBase + cb1); \
        asm volatile("cp.async.commit_group;" ::: "memory"); \
    } while (0)

    LOAD_STAGE(0, 0);

    for (int kb = 0; kb < 8; kb++) {
        int cur = kb & 1;
        asm volatile("cp.async.wait_group 0;" ::: "memory");
        __syncthreads();
        if (kb < 7) LOAD_STAGE(kb + 1, cur ^ 1);

        uint32_t a[2][4][4], b[2][4][2];
#pragma unroll
        for (int kh = 0; kh < 2; kh++) {
            int kk = kh * 16;
#pragma unroll
            for (int i = 0; i < 4; i++) {
                uint32_t ad = smem_u32(&As[cur][wm + i * 16 + (lane & 15)][kk + (lane >> 4) * 8]);
                asm volatile("ldmatrix.sync.aligned.m8n8.x4.shared.b16 {%0,%1,%2,%3}, [%4];"
                    : "=r"(a[kh][i][0]), "=r"(a[kh][i][1]), "=r"(a[kh][i][2]), "=r"(a[kh][i][3]) : "r"(ad));
            }
#pragma unroll
            for (int j2 = 0; j2 < 2; j2++) {
                uint32_t bd = smem_u32(&Bs[cur][kk + (lane & 15)][wn + j2 * 16 + (lane >> 4) * 8]);
                asm volatile("ldmatrix.sync.aligned.m8n8.x4.trans.shared.b16 {%0,%1,%2,%3}, [%4];"
                    : "=r"(b[kh][j2 * 2][0]), "=r"(b[kh][j2 * 2][1]),
                      "=r"(b[kh][j2 * 2 + 1][0]), "=r"(b[kh][j2 * 2 + 1][1]) : "r"(bd));
            }
        }
#pragma unroll
        for (int kh = 0; kh < 2; kh++)
#pragma unroll
            for (int i = 0; i < 4; i++)
#pragma unroll
                for (int j = 0; j < 4; j++)
                    asm volatile("mma.sync.aligned.m16n8k16.row.col.f32.f16.f16.f32 "
                        "{%0,%1,%2,%3}, {%4,%5,%6,%7}, {%8,%9}, {%0,%1,%2,%3};"
                        : "+f"(c[i][j][0]), "+f"(c[i][j][1]), "+f"(c[i][j][2]), "+f"(c[i][j][3])
                        : "r"(a[kh][i][0]), "r"(a[kh][i][1]), "r"(a[kh][i][2]), "r"(a[kh][i][3]),
                          "r"(b[kh][j][0]), "r"(b[kh][j][1]));
    }
#undef LOAD_STAGE

    if (colBase < nFeat) {
#pragma unroll
        for (int i = 0; i < 4; i++) {
            int row = rowBase + wm + i * 16 + (lane >> 2);
#pragma unroll
            for (int j = 0; j < 4; j++) {
                int col = colBase + wn + j * 8 + (lane & 3) * 2;
                if (row < NN)
                    *(__half2*)(F + (size_t)row * nFeat + col) = __floats2half2_rn(c[i][j][0], c[i][j][1]);
                if (row + 8 < NN)
                    *(__half2*)(F + (size_t)(row + 8) * nFeat + col) = __floats2half2_rn(c[i][j][2], c[i][j][3]);
            }
        }
    } else {
#pragma unroll
        for (int i = 0; i < 4; i++) {
            int row = rowBase + wm + i * 16 + (lane >> 2);
#pragma unroll
            for (int j = 0; j < 4; j++) {
                int col = colBase + wn + j * 8 + (lane & 3) * 2;
                if (row < NN)
                    *(float2*)(C + (size_t)row * Nc + col) = make_float2(c[i][j][0], c[i][j][1]);
                if (row + 8 < NN)
                    *(float2*)(C + (size_t)(row + 8) * Nc + col) = make_float2(c[i][j][2], c[i][j][3]);
            }
        }
    }
}

// ---------------- merged scatter + eedge ----------------
__global__ void __launch_bounds__(256) post_kernel(
        const int* __restrict__ src, const int* __restrict__ dst,
        const float* __restrict__ ef) {
    int blk = blockIdx.x, tid = threadIdx.x;
    if (blk < EE / 64) {
        __shared__ float sf[64][68];
        __shared__ float sw[64 * HH];
        int e0 = blk * 64;
        sw[tid] = g_wev[tid];
#pragma unroll
        for (int j = 0; j < 4; j++) {
            int idx = tid + j * 256;
            int e = idx >> 4, q = idx & 15;
            float4 v = *(const float4*)(ef + (size_t)(e0 + e) * 64 + q * 4);
            *(float4*)&sf[e][q * 4] = v;
        }
        __syncthreads();
        int e = tid >> 2, h = tid & 3;
        float acc = 0.f;
#pragma unroll
        for (int d = 0; d < 64; d++)
            acc = fmaf(sf[e][d], sw[d * 4 + h], acc);
        g_eedge[(size_t)(e0 + e) * 4 + h] = acc;
    } else {
        int e = (blk - EE / 64) * 256 + tid;
        if (e < EE) {
            int p = atomicAdd(&g_cur[dst[e]], 1);
            g_csrc[p] = src[e];
            g_ceid[p] = e;
        }
    }
}

// ---------------- CSR count + scan ----------------
__global__ void count_kernel(const int* __restrict__ dst) {
    int e = blockIdx.x * blockDim.x + threadIdx.x;
    if (e < EE) atomicAdd(&g_cur[dst[e]], 1);
}
__global__ void scan_kernel() {
    __shared__ int sh[1024];
    int t = threadIdx.x;
    int vals[10];
    int base = t * 10;
    int s = 0;
#pragma unroll
    for (int j = 0; j < 10; j++) {
        int idx = base + j;
        int v = (idx < NN) ? g_cur[idx] : 0;
        vals[j] = s;
        s += v;
    }
    sh[t] = s;
    __syncthreads();
    for (int off = 1; off < 1024; off <<= 1) {
        int v = (t >= off) ? sh[t - off] : 0;
        __syncthreads();
        sh[t] += v;
        __syncthreads();
    }
    int excl = (t > 0) ? sh[t - 1] : 0;
#pragma unroll
    for (int j = 0; j < 10; j++) {
        int idx = base + j;
        if (idx < NN) {
            int o = excl + vals[j];
            g_off[idx] = o;
            g_cur[idx] = o;
        }
    }
    if (t == 1023) g_off[NN] = sh[1023];
}

// ---------------- edge softmax: single pass ----------------
__global__ void alpha_kernel(const float* __restrict__ C, int D, int NCATP, int use_edge) {
    int warp = (blockIdx.x * blockDim.x + threadIdx.x) >> 5;
    int lane = threadIdx.x & 31;
    if (warp >= NN) return;
    int n = warp;
    int b = g_off[n];
    int deg4 = (g_off[n + 1] - b) * 4;
    int h = lane & 3;
    int colE = 5 * D;
    float ern = C[(size_t)n * NCATP + colE + 4 + h];

    float sum = 0.f;
    for (int t = lane; t < deg4; t += 32) {
        int p = b + (t >> 2);
        float e = C[(size_t)g_csrc[p] * NCATP + colE + h] + ern;
        if (use_edge) e += g_eedge[(size_t)g_ceid[p] * 4 + h];
        e = e > 0.f ? e : 0.2f * e;
        float ex = __expf(e);
        g_alpha[(size_t)p * 4 + h] = ex;
        sum += ex;
    }
    sum += __shfl_xor_sync(0xffffffffu, sum, 4);
    sum += __shfl_xor_sync(0xffffffffu, sum, 8);
    sum += __shfl_xor_sync(0xffffffffu, sum, 16);
    if (lane < 4) g_inv[n * 4 + h] = 1.f / (sum + 1e-9f);
}

// ---------------- aggregation: fp16 gather, 2x unrolled (+fp16 A2 write) -----
template <int D, int WRITE_F16>
__global__ void agg_kernel(const float* __restrict__ C, const __half* __restrict__ F,
                           float* __restrict__ out, int NCATP) {
    constexpr int DG = D / 4;
    constexpr int FW = 4 * D;
    int n = blockIdx.x;
    int tid = threadIdx.x;
    int h = tid / DG;
    int dg = tid % DG;
    int b = g_off[n], e = g_off[n + 1];
    float4 acc = make_float4(0.f, 0.f, 0.f, 0.f);
    const __half* fbase = F + h * D + dg * 4;

    int p = b;
    for (; p + 2 <= e; p += 2) {
        int s0 = g_csrc[p], s1 = g_csrc[p + 1];
        float a0 = g_alpha[(size_t)p * 4 + h];
        float a1 = g_alpha[(size_t)(p + 1) * 4 + h];
        uint2 r0 = *(const uint2*)(fbase + (size_t)s0 * FW);
        uint2 r1 = *(const uint2*)(fbase + (size_t)s1 * FW);
        float2 f00 = __half22float2(*reinterpret_cast<__half2*>(&r0.x));
        float2 f01 = __half22float2(*reinterpret_cast<__half2*>(&r0.y));
        float2 f10 = __half22float2(*reinterpret_cast<__half2*>(&r1.x));
        float2 f11 = __half22float2(*reinterpret_cast<__half2*>(&r1.y));
        acc.x = fmaf(a0, f00.x, acc.x);
        acc.y = fmaf(a0, f00.y, acc.y);
        acc.z = fmaf(a0, f01.x, acc.z);
        acc.w = fmaf(a0, f01.y, acc.w);
        acc.x = fmaf(a1, f10.x, acc.x);
        acc.y = fmaf(a1, f10.y, acc.y);
        acc.z = fmaf(a1, f11.x, acc.z);
        acc.w = fmaf(a1, f11.y, acc.w);
    }
    if (p < e) {
        int s0 = g_csrc[p];
        float a0 = g_alpha[(size_t)p * 4 + h];
        uint2 r0 = *(const uint2*)(fbase + (size_t)s0 * FW);
        float2 f00 = __half22float2(*reinterpret_cast<__half2*>(&r0.x));
        float2 f01 = __half22float2(*reinterpret_cast<__half2*>(&r0.y));
        acc.x = fmaf(a0, f00.x, acc.x);
        acc.y = fmaf(a0, f00.y, acc.y);
        acc.z = fmaf(a0, f01.x, acc.z);
        acc.w = fmaf(a0, f01.y, acc.w);
    }
    float sc = g_inv[n * 4 + h] * 0.25f;
    acc.x *= sc; acc.y *= sc; acc.z *= sc; acc.w *= sc;

    __shared__ float4 sh[4 * DG];
    sh[tid] = acc;
    __syncthreads();
    if (tid < DG) {
        float4 q0 = sh[tid], q1 = sh[DG + tid], q2 = sh[2 * DG + tid], q3 = sh[3 * DG + tid];
        float4 rr = *(const float4*)(C + (size_t)n * NCATP + 4 * D + tid * 4);
        float4 o;
        o.x = fmaxf(q0.x + q1.x + q2.x + q3.x + rr.x, 0.f);
        o.y = fmaxf(q0.y + q1.y + q2.y + q3.y + rr.y, 0.f);
        o.z = fmaxf(q0.z + q1.z + q2.z + q3.z + rr.z, 0.f);
        o.w = fmaxf(q0.w + q1.w + q2.w + q3.w + rr.w, 0.f);
        *(float4*)(out + (size_t)n * D + tid * 4) = o;
        if (WRITE_F16) {
            size_t base = (size_t)n * 256 + tid * 4;
            float vv[4] = {o.x, o.y, o.z, o.w};
#pragma unroll
            for (int j = 0; j < 4; j++) {
                __half hi, lo;
                f16split(vv[j], hi, lo);
                g_A2[base + j]       = hi;
                g_A2[base + 128 + j] = lo;
            }
        }
    }
}

// ---------------- host orchestration ----------------
extern "C" void kernel_launch(void* const* d_in, const int* in_sizes, int n_in,
                              void* d_out, int out_size) {
    const float* x0  = (const float*)d_in[0];
    const float* ef  = (const float*)d_in[1];
    const int*   src = (const int*)d_in[2];
    const int*   dst = (const int*)d_in[3];

    float *p_C, *p_hA, *p_hB;
    __half *p_F, *p_A2, *p_B2;
    cudaGetSymbolAddress((void**)&p_C,  g_C);
    cudaGetSymbolAddress((void**)&p_F,  g_F16);
    cudaGetSymbolAddress((void**)&p_hA, g_hA);
    cudaGetSymbolAddress((void**)&p_hB, g_hB);
    cudaGetSymbolAddress((void**)&p_A2, g_A2);
    cudaGetSymbolAddress((void**)&p_B2, g_B2);

    float* houts[4]  = {p_hA, p_hB, p_hA, (float*)d_out};
    int Dl[4]        = {128, 128, 128, 256};
    int NCATP_[4]    = {768, 768, 768, 1408};
    size_t B2OFF[4]  = {0, 196608, 393216, 589824};

    prep_kernel<<<6905, 256>>>(x0,
        (const float*)d_in[4],  (const float*)d_in[10], (const float*)d_in[14], (const float*)d_in[18],
        (const float*)d_in[9],  (const float*)d_in[13], (const float*)d_in[17], (const float*)d_in[21],
        (const float*)d_in[6],  (const float*)d_in[11], (const float*)d_in[15], (const float*)d_in[19],
        (const float*)d_in[7],  (const float*)d_in[12], (const float*)d_in[16], (const float*)d_in[20],
        (const float*)d_in[5],  (const float*)d_in[8]);
    count_kernel<<<(EE + 255) / 256, 256>>>(dst);
    scan_kernel<<<1, 1024>>>();
    {   // launch #4: L0 GEMM (profiled)
        dim3 gg(MPAD / 128, NCATP_[0] / 128);
        mma_gemm<<<gg, 256>>>(p_A2, p_B2 + B2OFF[0], p_C, p_F, NCATP_[0], 4 * Dl[0]);
    }
    post_kernel<<<EE / 64 + (EE + 255) / 256, 256>>>(src, dst, ef);
    alpha_kernel<<<(NN * 32 + 255) / 256, 256>>>(p_C, Dl[0], NCATP_[0], 1);
    agg_kernel<128, 1><<<NN, 128>>>(p_C, p_F, houts[0], NCATP_[0]);

    for (int L = 1; L < 4; L++) {
        int D = Dl[L];
        int NCATP = NCATP_[L];
        dim3 gg(MPAD / 128, NCATP / 128);
        mma_gemm<<<gg, 256>>>(p_A2, p_B2 + B2OFF[L], p_C, p_F, NCATP, 4 * D);
        alpha_kernel<<<(NN * 32 + 255) / 256, 256>>>(p_C, D, NCATP, 0);
        if (D == 128) {
            agg_kernel<128, 1><<<NN, 128>>>(p_C, p_F, houts[L], NCATP);
        } else {
            agg_kernel<256, 0><<<NN, 256>>>(p_C, p_F, houts[L], NCATP);
        }
    }
}

// round 13
// speedup vs baseline: 1.1299x; 1.0338x over previous
#include <cuda_runtime.h>
#include <cuda_fp16.h>
#include <math.h>
#include <stdint.h>

#define NN 10000
#define EE 160000
#define HH 4
#define MPAD 10112   // 79 * 128

// ---------------- static scratch ----------------
__device__ __half g_F16[NN * 1024];            // [N, 4*D] fp16 feat gather table
__device__ float  g_R  [NN * 256];             // [N, D] fp32 residual (compact)
__device__ float  g_EL [NN * 8];               // [N][el0..3 er0..3] fp32 (hot table)
__device__ __half g_A2[MPAD * 256];            // [M, 256] = [fp16 hi | fp16 lo]
__device__ __half g_B2[256 * 3712];            // 4 layers of [256][NCATP_l]
__device__ float g_hA  [NN * 128];
__device__ float g_hB  [NN * 128];
__device__ float g_eedge[EE * HH];
__device__ float g_inv [NN * HH];
__device__ float g_alpha[EE * HH];
__device__ int   g_off [NN + 1];
__device__ int   g_cur [NN];
__device__ int   g_csrc[EE];
__device__ int   g_ceid[EE];
__device__ float g_wev [64 * HH];

__device__ __forceinline__ uint32_t smem_u32(const void* p) {
    return (uint32_t)__cvta_generic_to_shared(p);
}
__device__ __forceinline__ void cpa16(uint32_t s, const void* g) {
    asm volatile("cp.async.cg.shared.global [%0], [%1], 16;" :: "r"(s), "l"(g));
}
__device__ __forceinline__ void f16split(float v, __half& hi, __half& lo) {
    hi = __float2half(v);
    lo = __float2half(v - __half2float(hi));
}

// ---------------- mega-prep ----------------
__global__ void prep_kernel(
    const float* __restrict__ x0,
    const float* W0, const float* W1, const float* W2, const float* W3,
    const float* r0, const float* r1, const float* r2, const float* r3,
    const float* al0, const float* al1, const float* al2, const float* al3,
    const float* ar0, const float* ar1, const float* ar2, const float* ar3,
    const float* We, const float* ae) {
    const float* W[4]  = {W0, W1, W2, W3};
    const float* rs[4] = {r0, r1, r2, r3};
    const float* al[4] = {al0, al1, al2, al3};
    const float* ar[4] = {ar0, ar1, ar2, ar3};
    const int Dl[4]    = {128, 128, 128, 256};
    const int NC[4]    = {768, 768, 768, 1408};
    const int B2OFF[4] = {0, 196608, 393216, 589824};

    int blk = blockIdx.x, tid = threadIdx.x;

    if (blk < 5000) {                       // conv_x: x0 -> A2 fp16 [hi|lo]
        int i = blk * 256 + tid;
        int row = i >> 7, col = i & 127;
        __half hi, lo;
        f16split(x0[i], hi, lo);
        size_t base = (size_t)row * 256 + col;
        g_A2[base]       = hi;
        g_A2[base + 128] = lo;
    } else if (blk < 6856) {                // B2 builds
        int l, base;
        if (blk < 5384)      { l = 0; base = blk - 5000; }
        else if (blk < 5768) { l = 1; base = blk - 5384; }
        else if (blk < 6152) { l = 2; base = blk - 5768; }
        else                 { l = 3; base = blk - 6152; }
        int NCATP = NC[l], D = Dl[l];
        int t = base * 256 + tid;
        int i = t / NCATP, c = t - i * NCATP;
        if (c >= 5 * D && c < 5 * D + 8) return;
        float v = 0.f;
        if (c < 4 * D)      v = W[l][(size_t)i * 4 * D + c];
        else if (c < 5 * D) v = rs[l][(size_t)i * D + (c - 4 * D)];
        __half hv = __float2half(v);
        size_t o = B2OFF[l];
        g_B2[o + (size_t)i * NCATP + c]         = hv;
        g_B2[o + (size_t)(i + 128) * NCATP + c] = hv;
    } else if (blk < 6864) {                // contract: el/er columns
        int lid = blk - 6856;
        int l = lid >> 1;
        int t = (lid & 1) * 256 + tid;
        int NCATP = NC[l], D = Dl[l];
        int i = t >> 2, h = t & 3;
        const float* wr = W[l] + (size_t)(i * HH + h) * D;
        const float* vl = al[l] + h * D;
        const float* vr = ar[l] + h * D;
        float sl = 0.f, sr = 0.f;
        for (int d = 0; d < D; d++) {
            float w = wr[d];
            sl = fmaf(w, vl[d], sl);
            sr = fmaf(w, vr[d], sr);
        }
        size_t o = B2OFF[l];
        int cL = 5 * D + h, cR = 5 * D + 4 + h;
        __half hl16 = __float2half(sl), hr16 = __float2half(sr);
        g_B2[o + (size_t)i * NCATP + cL]         = hl16;
        g_B2[o + (size_t)(i + 128) * NCATP + cL] = hl16;
        g_B2[o + (size_t)i * NCATP + cR]         = hr16;
        g_B2[o + (size_t)(i + 128) * NCATP + cR] = hr16;
    } else if (blk == 6864) {               // wev = We . ae
        int t = tid;
        int i = t >> 2, h = t & 3;
        const float* wr = We + (size_t)(i * HH + h) * 128;
        const float* a  = ae + h * 128;
        float s = 0.f;
        for (int d = 0; d < 128; d++) s = fmaf(wr[d], a[d], s);
        g_wev[t] = s;
    } else {                                // zero_cur
        int i = (blk - 6865) * 256 + tid;
        if (i < NN) g_cur[i] = 0;
    }
}

// ---------------- fp16 HMMA GEMM; epilogue routes to F16 / R / EL -----------
__global__ void __launch_bounds__(256) mma_gemm(
        const __half* __restrict__ A2, const __half* __restrict__ B2,
        __half* __restrict__ F, float* __restrict__ R, float* __restrict__ EL,
        int Nc, int nFeat, int D) {
    __shared__ __half As[2][128][40];
    __shared__ __half Bs[2][32][136];
    int tid = threadIdx.x, wid = tid >> 5, lane = tid & 31;
    int wm = (wid & 1) * 64;
    int wn = (wid >> 1) * 32;
    int rowBase = blockIdx.x * 128;
    int colBase = blockIdx.y * 128;

    float c[4][4][4];
#pragma unroll
    for (int i = 0; i < 4; i++)
#pragma unroll
        for (int j = 0; j < 4; j++)
#pragma unroll
            for (int r = 0; r < 4; r++) c[i][j][r] = 0.f;

    int ra0 = tid >> 2,          ca0 = (tid & 3) * 8;
    int ra1 = (tid + 256) >> 2,  ca1 = ((tid + 256) & 3) * 8;
    int rb0 = tid >> 4,          cb0 = (tid & 15) * 8;
    int rb1 = (tid + 256) >> 4,  cb1 = ((tid + 256) & 15) * 8;

#define LOAD_STAGE(kb, st) do { \
        int k0 = (kb) * 32; \
        cpa16(smem_u32(&As[st][ra0][ca0]), A2 + (size_t)(rowBase + ra0) * 256 + k0 + ca0); \
        cpa16(smem_u32(&As[st][ra1][ca1]), A2 + (size_t)(rowBase + ra1) * 256 + k0 + ca1); \
        cpa16(smem_u32(&Bs[st][rb0][cb0]), B2 + (size_t)(k0 + rb0) * Nc + colBase + cb0); \
        cpa16(smem_u32(&Bs[st][rb1][cb1]), B2 + (size_t)(k0 + rb1) * Nc + colBase + cb1); \
        asm volatile("cp.async.commit_group;" ::: "memory"); \
    } while (0)

    LOAD_STAGE(0, 0);

    for (int kb = 0; kb < 8; kb++) {
        int cur = kb & 1;
        asm volatile("cp.async.wait_group 0;" ::: "memory");
        __syncthreads();
        if (kb < 7) LOAD_STAGE(kb + 1, cur ^ 1);

        uint32_t a[2][4][4], b[2][4][2];
#pragma unroll
        for (int kh = 0; kh < 2; kh++) {
            int kk = kh * 16;
#pragma unroll
            for (int i = 0; i < 4; i++) {
                uint32_t ad = smem_u32(&As[cur][wm + i * 16 + (lane & 15)][kk + (lane >> 4) * 8]);
                asm volatile("ldmatrix.sync.aligned.m8n8.x4.shared.b16 {%0,%1,%2,%3}, [%4];"
                    : "=r"(a[kh][i][0]), "=r"(a[kh][i][1]), "=r"(a[kh][i][2]), "=r"(a[kh][i][3]) : "r"(ad));
            }
#pragma unroll
            for (int j2 = 0; j2 < 2; j2++) {
                uint32_t bd = smem_u32(&Bs[cur][kk + (lane & 15)][wn + j2 * 16 + (lane >> 4) * 8]);
                asm volatile("ldmatrix.sync.aligned.m8n8.x4.trans.shared.b16 {%0,%1,%2,%3}, [%4];"
                    : "=r"(b[kh][j2 * 2][0]), "=r"(b[kh][j2 * 2][1]),
                      "=r"(b[kh][j2 * 2 + 1][0]), "=r"(b[kh][j2 * 2 + 1][1]) : "r"(bd));
            }
        }
#pragma unroll
        for (int kh = 0; kh < 2; kh++)
#pragma unroll
            for (int i = 0; i < 4; i++)
#pragma unroll
                for (int j = 0; j < 4; j++)
                    asm volatile("mma.sync.aligned.m16n8k16.row.col.f32.f16.f16.f32 "
                        "{%0,%1,%2,%3}, {%4,%5,%6,%7}, {%8,%9}, {%0,%1,%2,%3};"
                        : "+f"(c[i][j][0]), "+f"(c[i][j][1]), "+f"(c[i][j][2]), "+f"(c[i][j][3])
                        : "r"(a[kh][i][0]), "r"(a[kh][i][1]), "r"(a[kh][i][2]), "r"(a[kh][i][3]),
                          "r"(b[kh][j][0]), "r"(b[kh][j][1]));
    }
#undef LOAD_STAGE

    if (colBase < nFeat) {
        // feat tile -> fp16 gather table
#pragma unroll
        for (int i = 0; i < 4; i++) {
            int row = rowBase + wm + i * 16 + (lane >> 2);
#pragma unroll
            for (int j = 0; j < 4; j++) {
                int col = colBase + wn + j * 8 + (lane & 3) * 2;
                if (row < NN)
                    *(__half2*)(F + (size_t)row * nFeat + col) = __floats2half2_rn(c[i][j][0], c[i][j][1]);
                if (row + 8 < NN)
                    *(__half2*)(F + (size_t)(row + 8) * nFeat + col) = __floats2half2_rn(c[i][j][2], c[i][j][3]);
            }
        }
    } else if (colBase < nFeat + D) {
        // res tile -> compact fp32 [N][D]
        int cbase = colBase - nFeat;
#pragma unroll
        for (int i = 0; i < 4; i++) {
            int row = rowBase + wm + i * 16 + (lane >> 2);
#pragma unroll
            for (int j = 0; j < 4; j++) {
                int col = cbase + wn + j * 8 + (lane & 3) * 2;
                if (row < NN)
                    *(float2*)(R + (size_t)row * D + col) = make_float2(c[i][j][0], c[i][j][1]);
                if (row + 8 < NN)
                    *(float2*)(R + (size_t)(row + 8) * D + col) = make_float2(c[i][j][2], c[i][j][3]);
            }
        }
    } else {
        // el/er tile: only cols [0,8) useful -> compact [N][8]; wn==0, j==0 only
        if (wn == 0) {
#pragma unroll
            for (int i = 0; i < 4; i++) {
                int row = rowBase + wm + i * 16 + (lane >> 2);
                int col = (lane & 3) * 2;
                if (row < NN)
                    *(float2*)(EL + (size_t)row * 8 + col) = make_float2(c[i][0][0], c[i][0][1]);
                if (row + 8 < NN)
                    *(float2*)(EL + (size_t)(row + 8) * 8 + col) = make_float2(c[i][0][2], c[i][0][3]);
            }
        }
    }
}

// ---------------- merged scatter + eedge ----------------
__global__ void __launch_bounds__(256) post_kernel(
        const int* __restrict__ src, const int* __restrict__ dst,
        const float* __restrict__ ef) {
    int blk = blockIdx.x, tid = threadIdx.x;
    if (blk < EE / 64) {
        __shared__ float sf[64][68];
        __shared__ float sw[64 * HH];
        int e0 = blk * 64;
        sw[tid] = g_wev[tid];
#pragma unroll
        for (int j = 0; j < 4; j++) {
            int idx = tid + j * 256;
            int e = idx >> 4, q = idx & 15;
            float4 v = *(const float4*)(ef + (size_t)(e0 + e) * 64 + q * 4);
            *(float4*)&sf[e][q * 4] = v;
        }
        __syncthreads();
        int e = tid >> 2, h = tid & 3;
        float acc = 0.f;
#pragma unroll
        for (int d = 0; d < 64; d++)
            acc = fmaf(sf[e][d], sw[d * 4 + h], acc);
        g_eedge[(size_t)(e0 + e) * 4 + h] = acc;
    } else {
        int e = (blk - EE / 64) * 256 + tid;
        if (e < EE) {
            int p = atomicAdd(&g_cur[dst[e]], 1);
            g_csrc[p] = src[e];
            g_ceid[p] = e;
        }
    }
}

// ---------------- CSR count + scan ----------------
__global__ void count_kernel(const int* __restrict__ dst) {
    int e = blockIdx.x * blockDim.x + threadIdx.x;
    if (e < EE) atomicAdd(&g_cur[dst[e]], 1);
}
__global__ void scan_kernel() {
    __shared__ int sh[1024];
    int t = threadIdx.x;
    int vals[10];
    int base = t * 10;
    int s = 0;
#pragma unroll
    for (int j = 0; j < 10; j++) {
        int idx = base + j;
        int v = (idx < NN) ? g_cur[idx] : 0;
        vals[j] = s;
        s += v;
    }
    sh[t] = s;
    __syncthreads();
    for (int off = 1; off < 1024; off <<= 1) {
        int v = (t >= off) ? sh[t - off] : 0;
        __syncthreads();
        sh[t] += v;
        __syncthreads();
    }
    int excl = (t > 0) ? sh[t - 1] : 0;
#pragma unroll
    for (int j = 0; j < 10; j++) {
        int idx = base + j;
        if (idx < NN) {
            int o = excl + vals[j];
            g_off[idx] = o;
            g_cur[idx] = o;
        }
    }
    if (t == 1023) g_off[NN] = sh[1023];
}

// ---------------- edge softmax: single pass, hot EL table ----------------
__global__ void alpha_kernel(int use_edge) {
    int warp = (blockIdx.x * blockDim.x + threadIdx.x) >> 5;
    int lane = threadIdx.x & 31;
    if (warp >= NN) return;
    int n = warp;
    int b = g_off[n];
    int deg4 = (g_off[n + 1] - b) * 4;
    int h = lane & 3;
    float ern = g_EL[(size_t)n * 8 + 4 + h];

    float sum = 0.f;
    for (int t = lane; t < deg4; t += 32) {
        int p = b + (t >> 2);
        float e = g_EL[(size_t)g_csrc[p] * 8 + h] + ern;
        if (use_edge) e += g_eedge[(size_t)g_ceid[p] * 4 + h];
        e = e > 0.f ? e : 0.2f * e;
        float ex = __expf(e);
        g_alpha[(size_t)p * 4 + h] = ex;
        sum += ex;
    }
    sum += __shfl_xor_sync(0xffffffffu, sum, 4);
    sum += __shfl_xor_sync(0xffffffffu, sum, 8);
    sum += __shfl_xor_sync(0xffffffffu, sum, 16);
    if (lane < 4) g_inv[n * 4 + h] = 1.f / (sum + 1e-9f);
}

// ---------------- aggregation: fp16 gather, compact res (+fp16 A2 write) -----
template <int D, int WRITE_F16>
__global__ void agg_kernel(const float* __restrict__ R, const __half* __restrict__ F,
                           float* __restrict__ out) {
    constexpr int DG = D / 4;
    constexpr int FW = 4 * D;
    int n = blockIdx.x;
    int tid = threadIdx.x;
    int h = tid / DG;
    int dg = tid % DG;
    int b = g_off[n], e = g_off[n + 1];
    float4 acc = make_float4(0.f, 0.f, 0.f, 0.f);
    const __half* fbase = F + h * D + dg * 4;

    int p = b;
    for (; p + 2 <= e; p += 2) {
        int s0 = g_csrc[p], s1 = g_csrc[p + 1];
        float a0 = g_alpha[(size_t)p * 4 + h];
        float a1 = g_alpha[(size_t)(p + 1) * 4 + h];
        uint2 r0 = *(const uint2*)(fbase + (size_t)s0 * FW);
        uint2 r1 = *(const uint2*)(fbase + (size_t)s1 * FW);
        float2 f00 = __half22float2(*reinterpret_cast<__half2*>(&r0.x));
        float2 f01 = __half22float2(*reinterpret_cast<__half2*>(&r0.y));
        float2 f10 = __half22float2(*reinterpret_cast<__half2*>(&r1.x));
        float2 f11 = __half22float2(*reinterpret_cast<__half2*>(&r1.y));
        acc.x = fmaf(a0, f00.x, acc.x);
        acc.y = fmaf(a0, f00.y, acc.y);
        acc.z = fmaf(a0, f01.x, acc.z);
        acc.w = fmaf(a0, f01.y, acc.w);
        acc.x = fmaf(a1, f10.x, acc.x);
        acc.y = fmaf(a1, f10.y, acc.y);
        acc.z = fmaf(a1, f11.x, acc.z);
        acc.w = fmaf(a1, f11.y, acc.w);
    }
    if (p < e) {
        int s0 = g_csrc[p];
        float a0 = g_alpha[(size_t)p * 4 + h];
        uint2 r0 = *(const uint2*)(fbase + (size_t)s0 * FW);
        float2 f00 = __half22float2(*reinterpret_cast<__half2*>(&r0.x));
        float2 f01 = __half22float2(*reinterpret_cast<__half2*>(&r0.y));
        acc.x = fmaf(a0, f00.x, acc.x);
        acc.y = fmaf(a0, f00.y, acc.y);
        acc.z = fmaf(a0, f01.x, acc.z);
        acc.w = fmaf(a0, f01.y, acc.w);
    }
    float sc = g_inv[n * 4 + h] * 0.25f;
    acc.x *= sc; acc.y *= sc; acc.z *= sc; acc.w *= sc;

    __shared__ float4 sh[4 * DG];
    sh[tid] = acc;
    __syncthreads();
    if (tid < DG) {
        float4 q0 = sh[tid], q1 = sh[DG + tid], q2 = sh[2 * DG + tid], q3 = sh[3 * DG + tid];
        float4 rr = *(const float4*)(R + (size_t)n * D + tid * 4);
        float4 o;
        o.x = fmaxf(q0.x + q1.x + q2.x + q3.x + rr.x, 0.f);
        o.y = fmaxf(q0.y + q1.y + q2.y + q3.y + rr.y, 0.f);
        o.z = fmaxf(q0.z + q1.z + q2.z + q3.z + rr.z, 0.f);
        o.w = fmaxf(q0.w + q1.w + q2.w + q3.w + rr.w, 0.f);
        *(float4*)(out + (size_t)n * D + tid * 4) = o;
        if (WRITE_F16) {
            size_t base = (size_t)n * 256 + tid * 4;
            float vv[4] = {o.x, o.y, o.z, o.w};
#pragma unroll
            for (int j = 0; j < 4; j++) {
                __half hi, lo;
                f16split(vv[j], hi, lo);
                g_A2[base + j]       = hi;
                g_A2[base + 128 + j] = lo;
            }
        }
    }
}

// ---------------- host orchestration ----------------
extern "C" void kernel_launch(void* const* d_in, const int* in_sizes, int n_in,
                              void* d_out, int out_size) {
    const float* x0  = (const float*)d_in[0];
    const float* ef  = (const float*)d_in[1];
    const int*   src = (const int*)d_in[2];
    const int*   dst = (const int*)d_in[3];

    float *p_R, *p_EL, *p_hA, *p_hB;
    __half *p_F, *p_A2, *p_B2;
    cudaGetSymbolAddress((void**)&p_R,  g_R);
    cudaGetSymbolAddress((void**)&p_EL, g_EL);
    cudaGetSymbolAddress((void**)&p_F,  g_F16);
    cudaGetSymbolAddress((void**)&p_hA, g_hA);
    cudaGetSymbolAddress((void**)&p_hB, g_hB);
    cudaGetSymbolAddress((void**)&p_A2, g_A2);
    cudaGetSymbolAddress((void**)&p_B2, g_B2);

    float* houts[4]  = {p_hA, p_hB, p_hA, (float*)d_out};
    int Dl[4]        = {128, 128, 128, 256};
    int NCATP_[4]    = {768, 768, 768, 1408};
    size_t B2OFF[4]  = {0, 196608, 393216, 589824};

    prep_kernel<<<6905, 256>>>(x0,
        (const float*)d_in[4],  (const float*)d_in[10], (const float*)d_in[14], (const float*)d_in[18],
        (const float*)d_in[9],  (const float*)d_in[13], (const float*)d_in[17], (const float*)d_in[21],
        (const float*)d_in[6],  (const float*)d_in[11], (const float*)d_in[15], (const float*)d_in[19],
        (const float*)d_in[7],  (const float*)d_in[12], (const float*)d_in[16], (const float*)d_in[20],
        (const float*)d_in[5],  (const float*)d_in[8]);
    count_kernel<<<(EE + 255) / 256, 256>>>(dst);
    scan_kernel<<<1, 1024>>>();
    {   // launch #4: L0 GEMM (profiled)
        dim3 gg(MPAD / 128, NCATP_[0] / 128);
        mma_gemm<<<gg, 256>>>(p_A2, p_B2 + B2OFF[0], p_F, p_R, p_EL, NCATP_[0], 4 * Dl[0], Dl[0]);
    }
    post_kernel<<<EE / 64 + (EE + 255) / 256, 256>>>(src, dst, ef);
    alpha_kernel<<<(NN * 32 + 255) / 256, 256>>>(1);
    agg_kernel<128, 1><<<NN, 128>>>(p_R, p_F, houts[0]);

    for (int L = 1; L < 4; L++) {
        int D = Dl[L];
        int NCATP = NCATP_[L];
        dim3 gg(MPAD / 128, NCATP / 128);
        mma_gemm<<<gg, 256>>>(p_A2, p_B2 + B2OFF[L], p_F, p_R, p_EL, NCATP, 4 * D, D);
        alpha_kernel<<<(NN * 32 + 255) / 256, 256>>>(0);
        if (D == 128) {
            agg_kernel<128, 1><<<NN, 128>>>(p_R, p_F, houts[L]);
        } else {
            agg_kernel<256, 0><<<NN, 256>>>(p_R, p_F, houts[L]);
        }
    }
}